// round 14
// baseline (speedup 1.0000x reference)
#include <cuda_runtime.h>
#include <cstdint>
#include <cstddef>

#define Bsz   64
#define Hd    512
#define Tlen  512
#define G4H   2048
#define Ed    256
#define NMAIN 128
#define NPROD 20
#define NCTA  (NMAIN + NPROD)
#define NTHR  512
#define HB    (Hd * Bsz)
#define PPAD  18
#define T0    128                 /* t < T0 produced by standalone kA */
#define NTAIL (Tlen - T0)

typedef unsigned long long ull;

// ---------------- device scratch (static, allowed) ----------------
__device__ __align__(256) float g_xg[(size_t)Tlen * G4H * Bsz];  // 256 MB
__device__ __align__(256) float g_h0[2 * HB];
__device__ __align__(256) float g_h1[2 * HB];
__device__ unsigned g_tcnt[NTAIL];   // per-t producer tile counters (reset each launch)
__device__ unsigned g_bar1;
__device__ unsigned g_bar2;

// ---------------- packed f32x2 helpers ----------------
__device__ __forceinline__ ull pk2f(float x) {
    ull r; asm("mov.b64 %0, {%1, %1};" : "=l"(r) : "f"(x)); return r;
}
__device__ __forceinline__ void ffma2(ull& a, ull h, ull w) {
    asm("fma.rn.f32x2 %0, %1, %2, %0;" : "+l"(a) : "l"(h), "l"(w));
}
__device__ __forceinline__ void up2(ull v, float& x, float& y) {
    unsigned lo, hi;
    asm("mov.b64 {%0, %1}, %2;" : "=r"(lo), "=r"(hi) : "l"(v));
    x = __uint_as_float(lo); y = __uint_as_float(hi);
}
__device__ __forceinline__ float sigm(float x) {
    return __fdividef(1.f, 1.f + __expf(-x));
}
__device__ __forceinline__ float tanh_fast(float x) {
    float e = __expf(2.f * x);
    return 1.f - __fdividef(2.f, e + 1.f);
}

// ---------------- split grid barriers (monotonic counters) ----------------
__device__ __forceinline__ void bar_arrive(unsigned* ctr) {
    if (threadIdx.x == 0)
        asm volatile("red.release.gpu.global.add.u32 [%0], 1;" :: "l"(ctr) : "memory");
}
__device__ __forceinline__ void bar_wait(unsigned* ctr, unsigned target) {
    if (threadIdx.x == 0) {
        unsigned v;
        do {
            asm volatile("ld.acquire.gpu.global.u32 %0, [%1];" : "=r"(v) : "l"(ctr) : "memory");
        } while (v < target);
    }
    __syncthreads();
}

// =================================================================
// Kernel A (fp32 f32x2, proven) — now only t < T0 (gridDim.x = T0)
// =================================================================
__global__ void __launch_bounds__(256) kA(const int* __restrict__ x,
                                          const float* __restrict__ emb,
                                          const float* __restrict__ Wih0,
                                          const float* __restrict__ b0) {
    __shared__ float ws[64 * 33];
    __shared__ float xs2[32 * 66];
    __shared__ int   xr[64];
    const int tid = threadIdx.x;
    const int t   = blockIdx.x;
    const int rb  = blockIdx.y * 64;
    if (tid < 64) xr[tid] = x[tid * Tlen + t];
    __syncthreads();

    ull accA[4], accB[4];
#pragma unroll
    for (int j = 0; j < 4; j++) { accA[j] = 0ull; accB[j] = 0ull; }
    const int r4 = tid >> 4;
    const int q4 = (tid & 15) * 4;

    for (int ec = 0; ec < Ed; ec += 32) {
#pragma unroll
        for (int i = 0; i < 8; i++) {
            int idx = tid + i * 256;
            int a = idx >> 5, e = idx & 31;
            ws[a * 33 + e] = Wih0[(rb + a) * Ed + ec + e];
            xs2[e * 66 + a] = emb[(size_t)xr[a] * Ed + ec + e];
        }
        __syncthreads();
#pragma unroll 8
        for (int e = 0; e < 32; e++) {
            ull x01 = *(const ull*)&xs2[e * 66 + q4];
            ull x23 = *(const ull*)&xs2[e * 66 + q4 + 2];
#pragma unroll
            for (int j = 0; j < 4; j++) {
                ull w2 = pk2f(ws[(r4 * 4 + j) * 33 + e]);
                ffma2(accA[j], x01, w2);
                ffma2(accB[j], x23, w2);
            }
        }
        __syncthreads();
    }
#pragma unroll
    for (int j = 0; j < 4; j++) {
        int row = rb + r4 * 4 + j;
        float bv = b0[row];
        float4 o;
        up2(accA[j], o.x, o.y);
        up2(accB[j], o.z, o.w);
        o.x += bv; o.y += bv; o.z += bv; o.w += bv;
        *(float4*)(g_xg + ((size_t)t * G4H + row) * Bsz + q4) = o;
    }
}

// =================================================================
__global__ void kzero() {
    int i = blockIdx.x * 256 + threadIdx.x;   // grid 256 -> 65536 = 2*HB
    g_h0[i] = 0.f;
    g_h1[i] = 0.f;
    if (i < NTAIL) g_tcnt[i] = 0u;
    if (i == 0) { g_bar1 = 0u; g_bar2 = 0u; }
}

// =================================================================
// lstm_rec: 148 CTAs x 512 threads.
//   blockIdx < 128 : main (R8-proven schedule + per-t xg ready check)
//   else           : producer (computes Xg tiles for t >= T0)
// main smem: wT0 8192f | wT1 16384f | pbuf 16*64*18 f  = 168KB
// producer smem: ws 64*33 | xs2 32*66 | xr (subset of same alloc)
// =================================================================
#define SM_WT0  0
#define SM_WT1  8192
#define SM_PBUF 24576
#define SM_TOTF (24576 + 16 * 64 * PPAD)
#define SMEMB   (SM_TOTF * 4)

template <int NK>
__device__ __forceinline__ void gemm2(ull (&acc)[4][4], const float* wT, int kw0,
                                      const float* __restrict__ hsrc, int kh0,
                                      int rh, int q) {
    const float4* hp = (const float4*)hsrc + q;
    float4 hbuf[8];
#pragma unroll
    for (int j = 0; j < 8; j++) hbuf[j] = __ldcg(hp + (size_t)(kh0 + j) * 16);
#pragma unroll 8
    for (int i = 0; i < NK; i++) {
        float4 hc = hbuf[i & 7];
        if (i + 8 < NK) hbuf[i & 7] = __ldcg(hp + (size_t)(kh0 + i + 8) * 16);
        const ulonglong2* wp = (const ulonglong2*)(wT + (kw0 + i) * 16 + rh * 8);
        ulonglong2 wa = wp[0];
        ulonglong2 wb = wp[1];
        ull h2;
        h2 = pk2f(hc.x);
        ffma2(acc[0][0], wa.x, h2); ffma2(acc[1][0], wa.y, h2);
        ffma2(acc[2][0], wb.x, h2); ffma2(acc[3][0], wb.y, h2);
        h2 = pk2f(hc.y);
        ffma2(acc[0][1], wa.x, h2); ffma2(acc[1][1], wa.y, h2);
        ffma2(acc[2][1], wb.x, h2); ffma2(acc[3][1], wb.y, h2);
        h2 = pk2f(hc.z);
        ffma2(acc[0][2], wa.x, h2); ffma2(acc[1][2], wa.y, h2);
        ffma2(acc[2][2], wb.x, h2); ffma2(acc[3][2], wb.y, h2);
        h2 = pk2f(hc.w);
        ffma2(acc[0][3], wa.x, h2); ffma2(acc[1][3], wa.y, h2);
        ffma2(acc[2][3], wb.x, h2); ffma2(acc[3][3], wb.y, h2);
    }
}

__device__ __forceinline__ void storep(float* pbuf, ull (&acc)[4][4],
                                       int w, int rh, int q) {
#pragma unroll
    for (int p = 0; p < 4; p++)
#pragma unroll
        for (int j = 0; j < 4; j++)
            *(ull*)&pbuf[(w * 64 + q * 4 + j) * PPAD + rh * 8 + 2 * p] = acc[p][j];
}

__global__ void __launch_bounds__(NTHR, 1) lstm_rec(const float* __restrict__ Whh0,
                                                    const float* __restrict__ Wih1,
                                                    const float* __restrict__ Whh1,
                                                    const float* __restrict__ b1,
                                                    const int* __restrict__ x,
                                                    const float* __restrict__ emb,
                                                    const float* __restrict__ Wih0,
                                                    const float* __restrict__ b0) {
    extern __shared__ float sm[];
    const int tid = threadIdx.x;

    if (blockIdx.x >= NMAIN) {
        // ===================== PRODUCER CTA =====================
        float* pws = sm;                       // [64 rows][33]
        float* pxs = sm + 64 * 33;             // [32 e][66 b]
        int*   pxr = (int*)(sm + 64 * 33 + 32 * 66);
        const int pid = blockIdx.x - NMAIN;
        const int r4  = tid >> 5;              // 0..15 -> rows r4*4..+3
        const int bp  = tid & 31;              // batch pair 2bp, 2bp+1
        const int NT  = NTAIL * 32;            // tiles (t-major)

        for (int gi = pid; gi < NT; gi += NPROD) {
            const int t  = T0 + (gi >> 5);
            const int rb = (gi & 31) << 6;
            if (tid < 64) pxr[tid] = x[tid * Tlen + t];
            __syncthreads();                   // also fences pws/pxs reuse

            ull acc[4];
#pragma unroll
            for (int j = 0; j < 4; j++) acc[j] = 0ull;

            for (int ec = 0; ec < Ed; ec += 32) {
#pragma unroll
                for (int i2 = 0; i2 < 4; i2++) {
                    int idx = tid + i2 * 512;
                    int a = idx >> 5, e = idx & 31;
                    pws[a * 33 + e] = Wih0[(rb + a) * Ed + ec + e];
                    pxs[e * 66 + a] = emb[(size_t)pxr[a] * Ed + ec + e];
                }
                __syncthreads();
#pragma unroll 8
                for (int e = 0; e < 32; e++) {
                    ull x01 = *(const ull*)&pxs[e * 66 + 2 * bp];
#pragma unroll
                    for (int j = 0; j < 4; j++)
                        ffma2(acc[j], x01, pk2f(pws[(r4 * 4 + j) * 33 + e]));
                }
                __syncthreads();
            }
#pragma unroll
            for (int j = 0; j < 4; j++) {
                int row = rb + r4 * 4 + j;
                float2 o;
                up2(acc[j], o.x, o.y);
                float bv = b0[row];
                o.x += bv; o.y += bv;
                *(float2*)(g_xg + ((size_t)t * G4H + row) * Bsz + 2 * bp) = o;
            }
            __threadfence();
            __syncthreads();
            if (tid == 0)
                asm volatile("red.release.gpu.global.add.u32 [%0], 1;"
                             :: "l"(&g_tcnt[t - T0]) : "memory");
        }
        return;
    }

    // ===================== MAIN CTA (R8-proven) =====================
    float* wT0  = sm + SM_WT0;
    float* wT1  = sm + SM_WT1;
    float* pbuf = sm + SM_PBUF;
    const int u0 = blockIdx.x * 4;

    for (int idx = tid; idx < 512 * 16; idx += NTHR) {
        int j = idx >> 9, k = idx & 511;
        int row = ((j & 3) << 9) + u0 + (j >> 2);
        wT0[k * 16 + j] = Whh0[row * Hd + k];
    }
    for (int idx = tid; idx < 1024 * 16; idx += NTHR) {
        int j = idx >> 10, k = idx & 1023;
        int row = ((j & 3) << 9) + u0 + (j >> 2);
        wT1[k * 16 + j] = (k < 512) ? Wih1[row * Hd + k] : Whh1[row * Hd + (k - 512)];
    }
    __syncthreads();

    const int w    = tid >> 5;
    const int lane = tid & 31;
    const int rh   = lane >> 4;
    const int q    = lane & 15;
    const int uu = tid >> 6;
    const int bb = tid & 63;
    float c0 = 0.f, c1 = 0.f;
    float b1v[4] = {0.f, 0.f, 0.f, 0.f};
    if (tid < 256)
#pragma unroll
        for (int g = 0; g < 4; g++) b1v[g] = b1[(g << 9) + u0 + uu];

    for (int t = 0; t < Tlen; t++) {
        const int p = t & 1;

        if (t >= T0) bar_wait(&g_tcnt[t - T0], 32u);   // xg(t) produced?

        float xgv[4] = {0.f, 0.f, 0.f, 0.f};
        if (tid < 256)
#pragma unroll
            for (int g = 0; g < 4; g++)
                xgv[g] = __ldcs(&g_xg[((size_t)t * G4H + (g << 9) + u0 + uu) * Bsz + bb]);

        // ========== phase 1: gates0 partials = Whh0[:, slice] @ h0_prev ==========
        {
            ull acc[4][4];
#pragma unroll
            for (int a = 0; a < 4; a++)
#pragma unroll
                for (int b = 0; b < 4; b++) acc[a][b] = 0ull;
            gemm2<32>(acc, wT0, w * 32, g_h0 + (p ^ 1) * HB, w * 32, rh, q);
            storep(pbuf, acc, w, rh, q);
        }
        __syncthreads();
        if (tid < 256) {
            float s[4] = {xgv[0], xgv[1], xgv[2], xgv[3]};
#pragma unroll
            for (int w16 = 0; w16 < 16; w16++) {
                const float* pp = &pbuf[(w16 * 64 + bb) * PPAD + uu * 4];
                float2 v0 = *(const float2*)pp;
                float2 v1 = *(const float2*)(pp + 2);
                s[0] += v0.x; s[1] += v0.y; s[2] += v1.x; s[3] += v1.y;
            }
            c0 = sigm(s[1]) * c0 + sigm(s[0]) * tanh_fast(s[2]);
            float h0n = sigm(s[3]) * tanh_fast(c0);
            g_h0[p * HB + (u0 + uu) * 64 + bb] = h0n;
        }
        __syncthreads();
        bar_arrive(&g_bar1);           // publish h0(t)

        // ========== phase 2: Whh1 @ h1_prev, then Wih1 @ h0n ==========
        ull acc2[4][4];
#pragma unroll
        for (int a = 0; a < 4; a++)
#pragma unroll
            for (int b = 0; b < 4; b++) acc2[a][b] = 0ull;

        bar_wait(&g_bar2, NMAIN * (unsigned)t);
        gemm2<32>(acc2, wT1, 512 + w * 32, g_h1 + (p ^ 1) * HB, w * 32, rh, q);
        bar_wait(&g_bar1, NMAIN * (unsigned)(t + 1));
        gemm2<32>(acc2, wT1, w * 32, g_h0 + p * HB, w * 32, rh, q);
        storep(pbuf, acc2, w, rh, q);

        __syncthreads();
        if (tid < 256) {
            float s[4] = {b1v[0], b1v[1], b1v[2], b1v[3]};
#pragma unroll
            for (int w16 = 0; w16 < 16; w16++) {
                const float* pp = &pbuf[(w16 * 64 + bb) * PPAD + uu * 4];
                float2 v0 = *(const float2*)pp;
                float2 v1 = *(const float2*)(pp + 2);
                s[0] += v0.x; s[1] += v0.y; s[2] += v1.x; s[3] += v1.y;
            }
            c1 = sigm(s[1]) * c1 + sigm(s[0]) * tanh_fast(s[2]);
            float h1n = sigm(s[3]) * tanh_fast(c1);
            g_h1[p * HB + (u0 + uu) * 64 + bb] = h1n;
        }
        __syncthreads();
        bar_arrive(&g_bar2);           // publish h1(t)
    }
}

// =================================================================
__global__ void __launch_bounds__(1024) kclf(const float* __restrict__ Wclf,
                                             const float* __restrict__ bclf,
                                             float* __restrict__ out) {
    __shared__ float red[1024];
    const int t  = threadIdx.x;
    const int o  = t & 1;
    const int b  = (t >> 1) & 63;
    const int ks = t >> 7;
    const float* h = g_h1 + HB;       // t=511 parity 1
    float s = 0.f;
#pragma unroll 8
    for (int i = 0; i < 64; i++) {
        int k = ks * 64 + i;
        s = fmaf(Wclf[o * Hd + k], h[k * 64 + b], s);
    }
    red[t] = s;
    __syncthreads();
    if (ks == 0) {
        float v = s + bclf[o];
#pragma unroll
        for (int w8 = 1; w8 < 8; w8++) v += red[t + w8 * 128];
        out[b * 2 + o] = v;
    }
}

// =================================================================
extern "C" void kernel_launch(void* const* d_in, const int* in_sizes, int n_in,
                              void* d_out, int out_size) {
    const int*   x    = (const int*)  d_in[0];
    const float* emb  = (const float*)d_in[1];
    const float* Wih0 = (const float*)d_in[2];
    const float* Whh0 = (const float*)d_in[3];
    const float* b0   = (const float*)d_in[4];
    const float* Wih1 = (const float*)d_in[5];
    const float* Whh1 = (const float*)d_in[6];
    const float* b1   = (const float*)d_in[7];
    const float* Wclf = (const float*)d_in[8];
    const float* bclf = (const float*)d_in[9];
    float* out = (float*)d_out;

    cudaFuncSetAttribute(lstm_rec, cudaFuncAttributeMaxDynamicSharedMemorySize, SMEMB);

    kzero<<<256, 256>>>();
    dim3 gA(T0, 32);
    kA<<<gA, 256>>>(x, emb, Wih0, b0);
    lstm_rec<<<NCTA, NTHR, SMEMB>>>(Whh0, Wih1, Whh1, b1, x, emb, Wih0, b0);
    kclf<<<1, 1024>>>(Wclf, bclf, out);
}

// round 15
// speedup vs baseline: 1.6428x; 1.6428x over previous
#include <cuda_runtime.h>
#include <cstdint>
#include <cstddef>

#define Bsz   64
#define Hd    512
#define Tlen  512
#define G4H   2048
#define Ed    256
#define NMAIN 128
#define NPROD 20
#define NCTA  (NMAIN + NPROD)
#define NTHR  512
#define HB    (Hd * Bsz)
#define PPAD  18
#define T0    192                 /* t < T0 produced by standalone kA */
#define NTAIL (Tlen - T0)         /* 320 = 16 per producer */

typedef unsigned long long ull;

// ---------------- device scratch (static, allowed) ----------------
__device__ __align__(256) float g_xg[(size_t)Tlen * G4H * Bsz];  // 256 MB
__device__ __align__(256) float g_h0[2 * HB];
__device__ __align__(256) float g_h1[2 * HB];
__device__ unsigned g_tcnt[NTAIL];   // per-t ready flags (reset each launch)
__device__ unsigned g_bar1;
__device__ unsigned g_bar2;

// ---------------- packed f32x2 helpers ----------------
__device__ __forceinline__ ull pk2f(float x) {
    ull r; asm("mov.b64 %0, {%1, %1};" : "=l"(r) : "f"(x)); return r;
}
__device__ __forceinline__ void ffma2(ull& a, ull h, ull w) {
    asm("fma.rn.f32x2 %0, %1, %2, %0;" : "+l"(a) : "l"(h), "l"(w));
}
__device__ __forceinline__ void up2(ull v, float& x, float& y) {
    unsigned lo, hi;
    asm("mov.b64 {%0, %1}, %2;" : "=r"(lo), "=r"(hi) : "l"(v));
    x = __uint_as_float(lo); y = __uint_as_float(hi);
}
__device__ __forceinline__ float sigm(float x) {
    return __fdividef(1.f, 1.f + __expf(-x));
}
__device__ __forceinline__ float tanh_fast(float x) {
    float e = __expf(2.f * x);
    return 1.f - __fdividef(2.f, e + 1.f);
}

// ---------------- split grid barriers (monotonic counters) ----------------
__device__ __forceinline__ void bar_arrive(unsigned* ctr) {
    if (threadIdx.x == 0)
        asm volatile("red.release.gpu.global.add.u32 [%0], 1;" :: "l"(ctr) : "memory");
}
__device__ __forceinline__ void bar_wait(unsigned* ctr, unsigned target) {
    if (threadIdx.x == 0) {
        unsigned v;
        do {
            asm volatile("ld.acquire.gpu.global.u32 %0, [%1];" : "=r"(v) : "l"(ctr) : "memory");
        } while (v < target);
    }
    __syncthreads();
}

// =================================================================
// Kernel A (fp32 f32x2, proven) — prefix t < T0 only
// =================================================================
__global__ void __launch_bounds__(256) kA(const int* __restrict__ x,
                                          const float* __restrict__ emb,
                                          const float* __restrict__ Wih0,
                                          const float* __restrict__ b0) {
    __shared__ float ws[64 * 33];
    __shared__ float xs2[32 * 66];
    __shared__ int   xr[64];
    const int tid = threadIdx.x;
    const int t   = blockIdx.x;
    const int rb  = blockIdx.y * 64;
    if (tid < 64) xr[tid] = x[tid * Tlen + t];
    __syncthreads();

    ull accA[4], accB[4];
#pragma unroll
    for (int j = 0; j < 4; j++) { accA[j] = 0ull; accB[j] = 0ull; }
    const int r4 = tid >> 4;
    const int q4 = (tid & 15) * 4;

    for (int ec = 0; ec < Ed; ec += 32) {
#pragma unroll
        for (int i = 0; i < 8; i++) {
            int idx = tid + i * 256;
            int a = idx >> 5, e = idx & 31;
            ws[a * 33 + e] = Wih0[(rb + a) * Ed + ec + e];
            xs2[e * 66 + a] = emb[(size_t)xr[a] * Ed + ec + e];
        }
        __syncthreads();
#pragma unroll 8
        for (int e = 0; e < 32; e++) {
            ull x01 = *(const ull*)&xs2[e * 66 + q4];
            ull x23 = *(const ull*)&xs2[e * 66 + q4 + 2];
#pragma unroll
            for (int j = 0; j < 4; j++) {
                ull w2 = pk2f(ws[(r4 * 4 + j) * 33 + e]);
                ffma2(accA[j], x01, w2);
                ffma2(accB[j], x23, w2);
            }
        }
        __syncthreads();
    }
#pragma unroll
    for (int j = 0; j < 4; j++) {
        int row = rb + r4 * 4 + j;
        float bv = b0[row];
        float4 o;
        up2(accA[j], o.x, o.y);
        up2(accB[j], o.z, o.w);
        o.x += bv; o.y += bv; o.z += bv; o.w += bv;
        *(float4*)(g_xg + ((size_t)t * G4H + row) * Bsz + q4) = o;
    }
}

// =================================================================
__global__ void kzero() {
    int i = blockIdx.x * 256 + threadIdx.x;   // grid 256 -> 65536 = 2*HB
    g_h0[i] = 0.f;
    g_h1[i] = 0.f;
    if (i < NTAIL) g_tcnt[i] = 0u;
    if (i == 0) { g_bar1 = 0u; g_bar2 = 0u; }
}

// =================================================================
// lstm_rec: 148 CTAs x 512 threads.
//   blockIdx < 128 : main (R8-proven schedule + per-t xg ready check)
//   else           : producer (full Xg[t] slabs for t >= T0, kA-grade loop)
// main smem: wT0 8192f | wT1 16384f | pbuf 16*64*18 f  = 168KB
// producer smem: pws[128*33] | pxs[32*66] | pxr[64]  (subset)
// =================================================================
#define SM_WT0  0
#define SM_WT1  8192
#define SM_PBUF 24576
#define SM_TOTF (24576 + 16 * 64 * PPAD)
#define SMEMB   (SM_TOTF * 4)

template <int NK>
__device__ __forceinline__ void gemm2(ull (&acc)[4][4], const float* wT, int kw0,
                                      const float* __restrict__ hsrc, int kh0,
                                      int rh, int q) {
    const float4* hp = (const float4*)hsrc + q;
    float4 hbuf[8];
#pragma unroll
    for (int j = 0; j < 8; j++) hbuf[j] = __ldcg(hp + (size_t)(kh0 + j) * 16);
#pragma unroll 8
    for (int i = 0; i < NK; i++) {
        float4 hc = hbuf[i & 7];
        if (i + 8 < NK) hbuf[i & 7] = __ldcg(hp + (size_t)(kh0 + i + 8) * 16);
        const ulonglong2* wp = (const ulonglong2*)(wT + (kw0 + i) * 16 + rh * 8);
        ulonglong2 wa = wp[0];
        ulonglong2 wb = wp[1];
        ull h2;
        h2 = pk2f(hc.x);
        ffma2(acc[0][0], wa.x, h2); ffma2(acc[1][0], wa.y, h2);
        ffma2(acc[2][0], wb.x, h2); ffma2(acc[3][0], wb.y, h2);
        h2 = pk2f(hc.y);
        ffma2(acc[0][1], wa.x, h2); ffma2(acc[1][1], wa.y, h2);
        ffma2(acc[2][1], wb.x, h2); ffma2(acc[3][1], wb.y, h2);
        h2 = pk2f(hc.z);
        ffma2(acc[0][2], wa.x, h2); ffma2(acc[1][2], wa.y, h2);
        ffma2(acc[2][2], wb.x, h2); ffma2(acc[3][2], wb.y, h2);
        h2 = pk2f(hc.w);
        ffma2(acc[0][3], wa.x, h2); ffma2(acc[1][3], wa.y, h2);
        ffma2(acc[2][3], wb.x, h2); ffma2(acc[3][3], wb.y, h2);
    }
}

__device__ __forceinline__ void storep(float* pbuf, ull (&acc)[4][4],
                                       int w, int rh, int q) {
#pragma unroll
    for (int p = 0; p < 4; p++)
#pragma unroll
        for (int j = 0; j < 4; j++)
            *(ull*)&pbuf[(w * 64 + q * 4 + j) * PPAD + rh * 8 + 2 * p] = acc[p][j];
}

__global__ void __launch_bounds__(NTHR, 1) lstm_rec(const float* __restrict__ Whh0,
                                                    const float* __restrict__ Wih1,
                                                    const float* __restrict__ Whh1,
                                                    const float* __restrict__ b1,
                                                    const int* __restrict__ x,
                                                    const float* __restrict__ emb,
                                                    const float* __restrict__ Wih0,
                                                    const float* __restrict__ b0) {
    extern __shared__ float sm[];
    const int tid = threadIdx.x;

    if (blockIdx.x >= NMAIN) {
        // ===================== PRODUCER CTA (kA-grade loop) =====================
        float* pws = sm;                         // [128 rows][33]
        float* pxs = sm + 128 * 33;              // [32 e][66 b]
        int*   pxr = (int*)(sm + 128 * 33 + 32 * 66);
        const int pid = blockIdx.x - NMAIN;
        const int r8  = tid >> 4;                // 0..31 -> rows r8*4..+3 (of 128)
        const int q4  = (tid & 15) * 4;          // batch base

        for (int t = T0 + pid; t < Tlen; t += NPROD) {
            if (tid < 64) pxr[tid] = x[tid * Tlen + t];
            __syncthreads();

            for (int rb = 0; rb < G4H; rb += 128) {
                ull accA[4], accB[4];
#pragma unroll
                for (int j = 0; j < 4; j++) { accA[j] = 0ull; accB[j] = 0ull; }

                for (int ec = 0; ec < Ed; ec += 32) {
#pragma unroll
                    for (int i = 0; i < 8; i++) {          // ws: 128x32
                        int idx = tid + i * 512;
                        int a = idx >> 5, e = idx & 31;
                        pws[a * 33 + e] = Wih0[(rb + a) * Ed + ec + e];
                    }
#pragma unroll
                    for (int i = 0; i < 4; i++) {          // pxs: 32x64
                        int idx = tid + i * 512;
                        int a = idx >> 5, e = idx & 31;    // a 0..63
                        pxs[e * 66 + a] = emb[(size_t)pxr[a] * Ed + ec + e];
                    }
                    __syncthreads();
#pragma unroll 8
                    for (int e = 0; e < 32; e++) {
                        ull x01 = *(const ull*)&pxs[e * 66 + q4];
                        ull x23 = *(const ull*)&pxs[e * 66 + q4 + 2];
#pragma unroll
                        for (int j = 0; j < 4; j++) {
                            ull w2 = pk2f(pws[(r8 * 4 + j) * 33 + e]);
                            ffma2(accA[j], x01, w2);
                            ffma2(accB[j], x23, w2);
                        }
                    }
                    __syncthreads();
                }
#pragma unroll
                for (int j = 0; j < 4; j++) {
                    int row = rb + r8 * 4 + j;
                    float bv = b0[row];
                    float4 o;
                    up2(accA[j], o.x, o.y);
                    up2(accB[j], o.z, o.w);
                    o.x += bv; o.y += bv; o.z += bv; o.w += bv;
                    *(float4*)(g_xg + ((size_t)t * G4H + row) * Bsz + q4) = o;
                }
            }
            __threadfence();
            __syncthreads();
            if (tid == 0)
                asm volatile("red.release.gpu.global.add.u32 [%0], 1;"
                             :: "l"(&g_tcnt[t - T0]) : "memory");
        }
        return;
    }

    // ===================== MAIN CTA (R8-proven) =====================
    float* wT0  = sm + SM_WT0;
    float* wT1  = sm + SM_WT1;
    float* pbuf = sm + SM_PBUF;
    const int u0 = blockIdx.x * 4;

    for (int idx = tid; idx < 512 * 16; idx += NTHR) {
        int j = idx >> 9, k = idx & 511;
        int row = ((j & 3) << 9) + u0 + (j >> 2);
        wT0[k * 16 + j] = Whh0[row * Hd + k];
    }
    for (int idx = tid; idx < 1024 * 16; idx += NTHR) {
        int j = idx >> 10, k = idx & 1023;
        int row = ((j & 3) << 9) + u0 + (j >> 2);
        wT1[k * 16 + j] = (k < 512) ? Wih1[row * Hd + k] : Whh1[row * Hd + (k - 512)];
    }
    __syncthreads();

    const int w    = tid >> 5;
    const int lane = tid & 31;
    const int rh   = lane >> 4;
    const int q    = lane & 15;
    const int uu = tid >> 6;
    const int bb = tid & 63;
    float c0 = 0.f, c1 = 0.f;
    float b1v[4] = {0.f, 0.f, 0.f, 0.f};
    if (tid < 256)
#pragma unroll
        for (int g = 0; g < 4; g++) b1v[g] = b1[(g << 9) + u0 + uu];

    for (int t = 0; t < Tlen; t++) {
        const int p = t & 1;

        if (t >= T0) bar_wait(&g_tcnt[t - T0], 1u);   // xg(t) slab ready?

        float xgv[4] = {0.f, 0.f, 0.f, 0.f};
        if (tid < 256)
#pragma unroll
            for (int g = 0; g < 4; g++)
                xgv[g] = __ldcs(&g_xg[((size_t)t * G4H + (g << 9) + u0 + uu) * Bsz + bb]);

        // ========== phase 1: gates0 partials = Whh0[:, slice] @ h0_prev ==========
        {
            ull acc[4][4];
#pragma unroll
            for (int a = 0; a < 4; a++)
#pragma unroll
                for (int b = 0; b < 4; b++) acc[a][b] = 0ull;
            gemm2<32>(acc, wT0, w * 32, g_h0 + (p ^ 1) * HB, w * 32, rh, q);
            storep(pbuf, acc, w, rh, q);
        }
        __syncthreads();
        if (tid < 256) {
            float s[4] = {xgv[0], xgv[1], xgv[2], xgv[3]};
#pragma unroll
            for (int w16 = 0; w16 < 16; w16++) {
                const float* pp = &pbuf[(w16 * 64 + bb) * PPAD + uu * 4];
                float2 v0 = *(const float2*)pp;
                float2 v1 = *(const float2*)(pp + 2);
                s[0] += v0.x; s[1] += v0.y; s[2] += v1.x; s[3] += v1.y;
            }
            c0 = sigm(s[1]) * c0 + sigm(s[0]) * tanh_fast(s[2]);
            float h0n = sigm(s[3]) * tanh_fast(c0);
            g_h0[p * HB + (u0 + uu) * 64 + bb] = h0n;
        }
        __syncthreads();
        bar_arrive(&g_bar1);           // publish h0(t)

        // ========== phase 2: Whh1 @ h1_prev, then Wih1 @ h0n ==========
        ull acc2[4][4];
#pragma unroll
        for (int a = 0; a < 4; a++)
#pragma unroll
            for (int b = 0; b < 4; b++) acc2[a][b] = 0ull;

        bar_wait(&g_bar2, NMAIN * (unsigned)t);
        gemm2<32>(acc2, wT1, 512 + w * 32, g_h1 + (p ^ 1) * HB, w * 32, rh, q);
        bar_wait(&g_bar1, NMAIN * (unsigned)(t + 1));
        gemm2<32>(acc2, wT1, w * 32, g_h0 + p * HB, w * 32, rh, q);
        storep(pbuf, acc2, w, rh, q);

        __syncthreads();
        if (tid < 256) {
            float s[4] = {b1v[0], b1v[1], b1v[2], b1v[3]};
#pragma unroll
            for (int w16 = 0; w16 < 16; w16++) {
                const float* pp = &pbuf[(w16 * 64 + bb) * PPAD + uu * 4];
                float2 v0 = *(const float2*)pp;
                float2 v1 = *(const float2*)(pp + 2);
                s[0] += v0.x; s[1] += v0.y; s[2] += v1.x; s[3] += v1.y;
            }
            c1 = sigm(s[1]) * c1 + sigm(s[0]) * tanh_fast(s[2]);
            float h1n = sigm(s[3]) * tanh_fast(c1);
            g_h1[p * HB + (u0 + uu) * 64 + bb] = h1n;
        }
        __syncthreads();
        bar_arrive(&g_bar2);           // publish h1(t)
    }
}

// =================================================================
__global__ void __launch_bounds__(1024) kclf(const float* __restrict__ Wclf,
                                             const float* __restrict__ bclf,
                                             float* __restrict__ out) {
    __shared__ float red[1024];
    const int t  = threadIdx.x;
    const int o  = t & 1;
    const int b  = (t >> 1) & 63;
    const int ks = t >> 7;
    const float* h = g_h1 + HB;       // t=511 parity 1
    float s = 0.f;
#pragma unroll 8
    for (int i = 0; i < 64; i++) {
        int k = ks * 64 + i;
        s = fmaf(Wclf[o * Hd + k], h[k * 64 + b], s);
    }
    red[t] = s;
    __syncthreads();
    if (ks == 0) {
        float v = s + bclf[o];
#pragma unroll
        for (int w8 = 1; w8 < 8; w8++) v += red[t + w8 * 128];
        out[b * 2 + o] = v;
    }
}

// =================================================================
extern "C" void kernel_launch(void* const* d_in, const int* in_sizes, int n_in,
                              void* d_out, int out_size) {
    const int*   x    = (const int*)  d_in[0];
    const float* emb  = (const float*)d_in[1];
    const float* Wih0 = (const float*)d_in[2];
    const float* Whh0 = (const float*)d_in[3];
    const float* b0   = (const float*)d_in[4];
    const float* Wih1 = (const float*)d_in[5];
    const float* Whh1 = (const float*)d_in[6];
    const float* b1   = (const float*)d_in[7];
    const float* Wclf = (const float*)d_in[8];
    const float* bclf = (const float*)d_in[9];
    float* out = (float*)d_out;

    cudaFuncSetAttribute(lstm_rec, cudaFuncAttributeMaxDynamicSharedMemorySize, SMEMB);

    kzero<<<256, 256>>>();
    dim3 gA(T0, 32);
    kA<<<gA, 256>>>(x, emb, Wih0, b0);
    lstm_rec<<<NCTA, NTHR, SMEMB>>>(Whh0, Wih1, Whh1, b1, x, emb, Wih0, b0);
    kclf<<<1, 1024>>>(Wclf, bclf, out);
}

// round 16
// speedup vs baseline: 1.6888x; 1.0280x over previous
#include <cuda_runtime.h>
#include <cstdint>
#include <cstddef>

#define Bsz  64
#define Hd   512
#define Tlen 512
#define G4H  2048
#define Ed   256
#define NCTA 128
#define NTHR 512
#define HB   (Hd * Bsz)
#define PPAD 18

typedef unsigned long long ull;

// ---------------- device scratch (static, allowed) ----------------
__device__ __align__(256) float g_xg[(size_t)Tlen * G4H * Bsz];  // 256 MB
__device__ __align__(256) float g_h0[2 * HB];
__device__ __align__(256) float g_h1[2 * HB];
__device__ unsigned g_bar1;   // monotonic arrive counters (reset by kzero each launch)
__device__ unsigned g_bar2;

// ---------------- packed f32x2 helpers ----------------
__device__ __forceinline__ ull pk2f(float x) {
    ull r; asm("mov.b64 %0, {%1, %1};" : "=l"(r) : "f"(x)); return r;
}
__device__ __forceinline__ void ffma2(ull& a, ull h, ull w) {
    asm("fma.rn.f32x2 %0, %1, %2, %0;" : "+l"(a) : "l"(h), "l"(w));
}
__device__ __forceinline__ void up2(ull v, float& x, float& y) {
    unsigned lo, hi;
    asm("mov.b64 {%0, %1}, %2;" : "=r"(lo), "=r"(hi) : "l"(v));
    x = __uint_as_float(lo); y = __uint_as_float(hi);
}
__device__ __forceinline__ float sigm(float x) {
    return __fdividef(1.f, 1.f + __expf(-x));
}
__device__ __forceinline__ float tanh_fast(float x) {
    float e = __expf(2.f * x);
    return 1.f - __fdividef(2.f, e + 1.f);   // saturates to +/-1, NaN-free
}

// ---------------- split grid barrier: monotonic release/acquire ----------------
__device__ __forceinline__ void bar_arrive(unsigned* ctr) {
    if (threadIdx.x == 0)
        asm volatile("red.release.gpu.global.add.u32 [%0], 1;" :: "l"(ctr) : "memory");
}
__device__ __forceinline__ void bar_wait(unsigned* ctr, unsigned target) {
    if (threadIdx.x == 0) {
        unsigned v;
        do {
            asm volatile("ld.acquire.gpu.global.u32 %0, [%1];" : "=r"(v) : "l"(ctr) : "memory");
        } while (v < target);
    }
    __syncthreads();
}

// =================================================================
// Kernel A: Xg[t][row][b] = b0[row] + sum_e emb[x[b,t],e] * Wih0[row,e]
// =================================================================
__global__ void __launch_bounds__(256) kA(const int* __restrict__ x,
                                          const float* __restrict__ emb,
                                          const float* __restrict__ Wih0,
                                          const float* __restrict__ b0) {
    __shared__ float ws[64 * 33];      // [row][e]
    __shared__ float xs2[32 * 66];     // [e][b] transposed, padded
    __shared__ int   xr[64];
    const int tid = threadIdx.x;
    const int t   = blockIdx.x;
    const int rb  = blockIdx.y * 64;
    if (tid < 64) xr[tid] = x[tid * Tlen + t];
    __syncthreads();

    ull accA[4], accB[4];
#pragma unroll
    for (int j = 0; j < 4; j++) { accA[j] = 0ull; accB[j] = 0ull; }
    const int r4 = tid >> 4;
    const int q4 = (tid & 15) * 4;

    for (int ec = 0; ec < Ed; ec += 32) {
#pragma unroll
        for (int i = 0; i < 8; i++) {
            int idx = tid + i * 256;
            int a = idx >> 5, e = idx & 31;
            ws[a * 33 + e] = Wih0[(rb + a) * Ed + ec + e];
            xs2[e * 66 + a] = emb[(size_t)xr[a] * Ed + ec + e];
        }
        __syncthreads();
#pragma unroll 8
        for (int e = 0; e < 32; e++) {
            ull x01 = *(const ull*)&xs2[e * 66 + q4];
            ull x23 = *(const ull*)&xs2[e * 66 + q4 + 2];
#pragma unroll
            for (int j = 0; j < 4; j++) {
                ull w2 = pk2f(ws[(r4 * 4 + j) * 33 + e]);
                ffma2(accA[j], x01, w2);
                ffma2(accB[j], x23, w2);
            }
        }
        __syncthreads();
    }
#pragma unroll
    for (int j = 0; j < 4; j++) {
        int row = rb + r4 * 4 + j;
        float bv = b0[row];
        float4 o;
        up2(accA[j], o.x, o.y);
        up2(accB[j], o.z, o.w);
        o.x += bv; o.y += bv; o.z += bv; o.w += bv;
        *(float4*)(g_xg + ((size_t)t * G4H + row) * Bsz + q4) = o;
    }
}

// =================================================================
__global__ void kzero() {
    int i = blockIdx.x * 256 + threadIdx.x;   // grid 256 -> 65536 = 2*HB
    g_h0[i] = 0.f;
    g_h1[i] = 0.f;
    if (i == 0) { g_bar1 = 0u; g_bar2 = 0u; }
}

// =================================================================
// Persistent recurrent kernel: 128 CTAs x 512 threads (16 warps).
// R8-proven schedule; reduce now split across all 512 threads
// (each sums 8 partials; upper half stages via red2 smem).
// smem: wT0[512][16] | wT1[1024][16] | pbuf[16][64][18] | red2[256][4]
// =================================================================
#define SM_WT0  0
#define SM_WT1  8192
#define SM_PBUF 24576
#define SM_RED2 (24576 + 16 * 64 * PPAD)
#define SM_TOTF (SM_RED2 + 256 * 4)
#define SMEMB   (SM_TOTF * 4)

template <int NK>
__device__ __forceinline__ void gemm2(ull (&acc)[4][4], const float* wT, int kw0,
                                      const float* __restrict__ hsrc, int kh0,
                                      int rh, int q) {
    const float4* hp = (const float4*)hsrc + q;
    float4 hbuf[8];
#pragma unroll
    for (int j = 0; j < 8; j++) hbuf[j] = __ldcg(hp + (size_t)(kh0 + j) * 16);
#pragma unroll 8
    for (int i = 0; i < NK; i++) {
        float4 hc = hbuf[i & 7];
        if (i + 8 < NK) hbuf[i & 7] = __ldcg(hp + (size_t)(kh0 + i + 8) * 16);
        const ulonglong2* wp = (const ulonglong2*)(wT + (kw0 + i) * 16 + rh * 8);
        ulonglong2 wa = wp[0];
        ulonglong2 wb = wp[1];
        ull h2;
        h2 = pk2f(hc.x);
        ffma2(acc[0][0], wa.x, h2); ffma2(acc[1][0], wa.y, h2);
        ffma2(acc[2][0], wb.x, h2); ffma2(acc[3][0], wb.y, h2);
        h2 = pk2f(hc.y);
        ffma2(acc[0][1], wa.x, h2); ffma2(acc[1][1], wa.y, h2);
        ffma2(acc[2][1], wb.x, h2); ffma2(acc[3][1], wb.y, h2);
        h2 = pk2f(hc.z);
        ffma2(acc[0][2], wa.x, h2); ffma2(acc[1][2], wa.y, h2);
        ffma2(acc[2][2], wb.x, h2); ffma2(acc[3][2], wb.y, h2);
        h2 = pk2f(hc.w);
        ffma2(acc[0][3], wa.x, h2); ffma2(acc[1][3], wa.y, h2);
        ffma2(acc[2][3], wb.x, h2); ffma2(acc[3][3], wb.y, h2);
    }
}

__device__ __forceinline__ void storep(float* pbuf, ull (&acc)[4][4],
                                       int w, int rh, int q) {
#pragma unroll
    for (int p = 0; p < 4; p++)
#pragma unroll
        for (int j = 0; j < 4; j++)
            *(ull*)&pbuf[(w * 64 + q * 4 + j) * PPAD + rh * 8 + 2 * p] = acc[p][j];
}

// half-reduce: every thread sums 8 of the 16 partials for its (uu,bb)
__device__ __forceinline__ void halfred(const float* pbuf, int half, int uu2, int bb2,
                                        float& s0, float& s1, float& s2, float& s3) {
    s0 = 0.f; s1 = 0.f; s2 = 0.f; s3 = 0.f;
    const int base = half * 8;
#pragma unroll
    for (int w8 = 0; w8 < 8; w8++) {
        const float* pp = &pbuf[((base + w8) * 64 + bb2) * PPAD + uu2 * 4];
        float2 v0 = *(const float2*)pp;
        float2 v1 = *(const float2*)(pp + 2);
        s0 += v0.x; s1 += v0.y; s2 += v1.x; s3 += v1.y;
    }
}

__global__ void __launch_bounds__(NTHR, 1) lstm_rec(const float* __restrict__ Whh0,
                                                    const float* __restrict__ Wih1,
                                                    const float* __restrict__ Whh1,
                                                    const float* __restrict__ b1) {
    extern __shared__ float sm[];
    float* wT0  = sm + SM_WT0;
    float* wT1  = sm + SM_WT1;
    float* pbuf = sm + SM_PBUF;
    float* red2 = sm + SM_RED2;

    const int tid = threadIdx.x;
    const int u0  = blockIdx.x * 4;

    for (int idx = tid; idx < 512 * 16; idx += NTHR) {
        int j = idx >> 9, k = idx & 511;
        int row = ((j & 3) << 9) + u0 + (j >> 2);
        wT0[k * 16 + j] = Whh0[row * Hd + k];
    }
    for (int idx = tid; idx < 1024 * 16; idx += NTHR) {
        int j = idx >> 10, k = idx & 1023;
        int row = ((j & 3) << 9) + u0 + (j >> 2);
        wT1[k * 16 + j] = (k < 512) ? Wih1[row * Hd + k] : Whh1[row * Hd + (k - 512)];
    }
    __syncthreads();

    // gemm role
    const int w    = tid >> 5;
    const int lane = tid & 31;
    const int rh   = lane >> 4;
    const int q    = lane & 15;
    // reduce/update role (all threads reduce; tid<256 updates)
    const int half = tid >> 8;          // 0/1
    const int uu   = (tid >> 6) & 3;
    const int bb   = tid & 63;
    float c0 = 0.f, c1 = 0.f;
    float b1v[4] = {0.f, 0.f, 0.f, 0.f};
    if (tid < 256)
#pragma unroll
        for (int g = 0; g < 4; g++) b1v[g] = b1[(g << 9) + u0 + uu];

    for (int t = 0; t < Tlen; t++) {
        const int p = t & 1;

        float xgv[4] = {0.f, 0.f, 0.f, 0.f};
        if (tid < 256)
#pragma unroll
            for (int g = 0; g < 4; g++)
                xgv[g] = __ldcs(&g_xg[((size_t)t * G4H + (g << 9) + u0 + uu) * Bsz + bb]);

        // ========== phase 1: gates0 partials = Whh0[:, slice] @ h0_prev ==========
        {
            ull acc[4][4];
#pragma unroll
            for (int a = 0; a < 4; a++)
#pragma unroll
                for (int b = 0; b < 4; b++) acc[a][b] = 0ull;
            gemm2<32>(acc, wT0, w * 32, g_h0 + (p ^ 1) * HB, w * 32, rh, q);
            storep(pbuf, acc, w, rh, q);
        }
        __syncthreads();
        float rs0, rs1, rs2, rs3;
        halfred(pbuf, half, uu, bb, rs0, rs1, rs2, rs3);
        if (half) {
            float4 v = make_float4(rs0, rs1, rs2, rs3);
            *(float4*)&red2[(tid & 255) * 4] = v;
        }
        __syncthreads();
        if (tid < 256) {
            float4 v = *(const float4*)&red2[tid * 4];
            float s0 = xgv[0] + rs0 + v.x;
            float s1 = xgv[1] + rs1 + v.y;
            float s2 = xgv[2] + rs2 + v.z;
            float s3 = xgv[3] + rs3 + v.w;
            c0 = sigm(s1) * c0 + sigm(s0) * tanh_fast(s2);
            float h0n = sigm(s3) * tanh_fast(c0);
            g_h0[p * HB + (u0 + uu) * 64 + bb] = h0n;
        }
        __syncthreads();               // h0n stores + red2/pbuf reads complete
        bar_arrive(&g_bar1);           // publish h0(t)

        // ========== phase 2: Whh1 @ h1_prev, then Wih1 @ h0n ==========
        ull acc2[4][4];
#pragma unroll
        for (int a = 0; a < 4; a++)
#pragma unroll
            for (int b = 0; b < 4; b++) acc2[a][b] = 0ull;

        bar_wait(&g_bar2, NCTA * (unsigned)t);
        gemm2<32>(acc2, wT1, 512 + w * 32, g_h1 + (p ^ 1) * HB, w * 32, rh, q);
        bar_wait(&g_bar1, NCTA * (unsigned)(t + 1));
        gemm2<32>(acc2, wT1, w * 32, g_h0 + p * HB, w * 32, rh, q);
        storep(pbuf, acc2, w, rh, q);

        __syncthreads();
        halfred(pbuf, half, uu, bb, rs0, rs1, rs2, rs3);
        if (half) {
            float4 v = make_float4(rs0, rs1, rs2, rs3);
            *(float4*)&red2[(tid & 255) * 4] = v;
        }
        __syncthreads();
        if (tid < 256) {
            float4 v = *(const float4*)&red2[tid * 4];
            float s0 = b1v[0] + rs0 + v.x;
            float s1 = b1v[1] + rs1 + v.y;
            float s2 = b1v[2] + rs2 + v.z;
            float s3 = b1v[3] + rs3 + v.w;
            c1 = sigm(s1) * c1 + sigm(s0) * tanh_fast(s2);
            float h1n = sigm(s3) * tanh_fast(c1);
            g_h1[p * HB + (u0 + uu) * 64 + bb] = h1n;
        }
        __syncthreads();               // h1n stores + red2/pbuf reads complete
        bar_arrive(&g_bar2);           // publish h1(t)
    }
}

// =================================================================
// classifier: 1024 threads, k split 8 ways + smem tree
// =================================================================
__global__ void __launch_bounds__(1024) kclf(const float* __restrict__ Wclf,
                                             const float* __restrict__ bclf,
                                             float* __restrict__ out) {
    __shared__ float red[1024];
    const int t  = threadIdx.x;
    const int o  = t & 1;
    const int b  = (t >> 1) & 63;
    const int ks = t >> 7;
    const float* h = g_h1 + HB;       // parity of t=511 is 1
    float s = 0.f;
#pragma unroll 8
    for (int i = 0; i < 64; i++) {
        int k = ks * 64 + i;
        s = fmaf(Wclf[o * Hd + k], h[k * 64 + b], s);
    }
    red[t] = s;
    __syncthreads();
    if (ks == 0) {
        float v = s + bclf[o];
#pragma unroll
        for (int w8 = 1; w8 < 8; w8++) v += red[t + w8 * 128];
        out[b * 2 + o] = v;
    }
}

// =================================================================
extern "C" void kernel_launch(void* const* d_in, const int* in_sizes, int n_in,
                              void* d_out, int out_size) {
    const int*   x    = (const int*)  d_in[0];
    const float* emb  = (const float*)d_in[1];
    const float* Wih0 = (const float*)d_in[2];
    const float* Whh0 = (const float*)d_in[3];
    const float* b0   = (const float*)d_in[4];
    const float* Wih1 = (const float*)d_in[5];
    const float* Whh1 = (const float*)d_in[6];
    const float* b1   = (const float*)d_in[7];
    const float* Wclf = (const float*)d_in[8];
    const float* bclf = (const float*)d_in[9];
    float* out = (float*)d_out;

    cudaFuncSetAttribute(lstm_rec, cudaFuncAttributeMaxDynamicSharedMemorySize, SMEMB);

    kzero<<<256, 256>>>();
    dim3 gA(Tlen, 32);
    kA<<<gA, 256>>>(x, emb, Wih0, b0);
    lstm_rec<<<NCTA, NTHR, SMEMB>>>(Whh0, Wih1, Whh1, b1);
    kclf<<<1, 1024>>>(Wclf, bclf, out);
}